// round 15
// baseline (speedup 1.0000x reference)
#include <cuda_runtime.h>
#include <stdint.h>

#define D_MODEL 1024
#define FFN_DIM 4096
#define N_HEADS 16
#define HEAD_DIM 64
#define SEQLEN 2048
#define BATCH 2
#define NTOK (BATCH * SEQLEN)

// ---------------- scratch (device globals: no runtime allocation) ----------
__device__ float g_q[NTOK * D_MODEL];
__device__ float g_k[NTOK * D_MODEL];
__device__ float g_v[NTOK * D_MODEL];
__device__ float g_ctx[NTOK * D_MODEL];
__device__ float g_x1[NTOK * D_MODEL];
__device__ float g_x2[NTOK * D_MODEL];
__device__ float g_ffn[(size_t)NTOK * FFN_DIM];

// ---------------- tf32 helpers ---------------------------------------------
__device__ __forceinline__ uint32_t f2tf32(float x) {
    uint32_t r;
    asm("cvt.rna.tf32.f32 %0, %1;" : "=r"(r) : "f"(x));
    return r;
}

__device__ __forceinline__ float ex2f(float x) {
    float r;
    asm("ex2.approx.ftz.f32 %0, %1;" : "=f"(r) : "f"(x));
    return r;
}

__device__ __forceinline__ void mma_tf32(
    float* c, const uint32_t* a, const uint32_t* b)
{
    asm volatile(
        "mma.sync.aligned.m16n8k8.row.col.f32.tf32.tf32.f32 "
        "{%0,%1,%2,%3}, {%4,%5,%6,%7}, {%8,%9}, {%0,%1,%2,%3};\n"
        : "+f"(c[0]), "+f"(c[1]), "+f"(c[2]), "+f"(c[3])
        : "r"(a[0]), "r"(a[1]), "r"(a[2]), "r"(a[3]),
          "r"(b[0]), "r"(b[1]));
}

__device__ __forceinline__ void cp_async16(uint32_t dst_smem, const void* src) {
    asm volatile("cp.async.ca.shared.global [%0], [%1], 16;"
                 :: "r"(dst_smem), "l"(src));
}
__device__ __forceinline__ void cp_async_commit() {
    asm volatile("cp.async.commit_group;");
}
__device__ __forceinline__ void cp_async_wait0() {
    asm volatile("cp.async.wait_group 0;" ::: "memory");
}
__device__ __forceinline__ void cp_async_wait2() {
    asm volatile("cp.async.wait_group 2;" ::: "memory");
}

// ---------------- GEMM: 128x128 tile, 4 warps, warp tile 64x64 -------------
// C[M,Nper] = A[M,K] @ W[K,Nper] + bias (opt ReLU), up to 3 (A,W,bias,C)
// tuples per launch. 128 threads = 4 warps as 2m x 2n; 4x8 mmas per warp.
// 4-stage cp.async; smem raw f32: A [4][128][20], B [4][16][136].
// Per-mma overhead: 1 scalar LDS + 1 cvt (R12 was 1.5 + 1.5).
#define GA_ST 20
#define GB_ST 136
#define GEMM_SMEM ((4 * 128 * GA_ST + 4 * 16 * GB_ST) * 4)   // 75776 B

template <int RELU>
__global__ __launch_bounds__(128, 2) void gemm_cp_kernel(
    const float* __restrict__ A0, const float* __restrict__ W0,
    const float* __restrict__ bias0, float* __restrict__ C0,
    const float* __restrict__ A1, const float* __restrict__ W1,
    const float* __restrict__ bias1, float* __restrict__ C1,
    const float* __restrict__ A2, const float* __restrict__ W2,
    const float* __restrict__ bias2, float* __restrict__ C2,
    int M, int N, int K, int bpm)
{
    extern __shared__ float gsm[];
    float* Asm = gsm;                    // [4][128][GA_ST]
    float* Bsm = gsm + 4 * 128 * GA_ST;  // [4][16][GB_ST]

    const int tid  = threadIdx.x;
    const int lane = tid & 31;
    const int warp = tid >> 5;                   // 0..3
    const int wm = warp >> 1, wn = warp & 1;     // 2m x 2n
    const int la3 = lane & 3, lr = lane >> 2;
    const int mat = blockIdx.x / bpm;
    const int colBase = (blockIdx.x % bpm) * 128;
    const int rowBase = blockIdx.y * 128;

    const float* A    = (mat == 0) ? A0    : (mat == 1) ? A1    : A2;
    const float* W    = (mat == 0) ? W0    : (mat == 1) ? W1    : W2;
    const float* bias = (mat == 0) ? bias0 : (mat == 1) ? bias1 : bias2;
    float*       C    = (mat == 0) ? C0    : (mat == 1) ? C1    : C2;

    const uint32_t a_base = (uint32_t)__cvta_generic_to_shared(Asm);
    const uint32_t b_base = (uint32_t)__cvta_generic_to_shared(Bsm);

    // loader coordinates (128 threads)
    // A: thread t owns row t (128 rows), 4 chunks of 4 floats (k 0..15)
    // B: thread t owns rows (t>>4) and (t>>4)+8, 8 cols starting (t&15)*8
    const int bK  = tid >> 4;              // 0..7
    const int bN8 = (tid & 15) * 8;        // 0..120

    const float* Abase = A + (size_t)(rowBase + tid) * K;
    const float* Wbase = W + (size_t)bK * N + colBase + bN8;

    float acc[4][8][4];
#pragma unroll
    for (int i = 0; i < 4; i++)
#pragma unroll
        for (int j = 0; j < 8; j++)
#pragma unroll
            for (int r = 0; r < 4; r++) acc[i][j][r] = 0.f;

    const int nstages = K / 16;

    auto issue_stage = [&](int s) {
        if (s < nstages) {
            const int k0 = s * 16;
            const int st = s & 3;
            const float* Ap = Abase + k0;
            const uint32_t abuf = a_base + (uint32_t)((st * 128 + tid) * GA_ST) * 4;
            cp_async16(abuf,      Ap);
            cp_async16(abuf + 16, Ap + 4);
            cp_async16(abuf + 32, Ap + 8);
            cp_async16(abuf + 48, Ap + 12);
            const float* Wp = Wbase + (size_t)k0 * N;
            const uint32_t bbuf0 = b_base + (uint32_t)(((st * 16 + bK) * GB_ST + bN8) * 4);
            const uint32_t bbuf1 = b_base + (uint32_t)(((st * 16 + bK + 8) * GB_ST + bN8) * 4);
            cp_async16(bbuf0,      Wp);
            cp_async16(bbuf0 + 16, Wp + 4);
            cp_async16(bbuf1,      Wp + (size_t)8 * N);
            cp_async16(bbuf1 + 16, Wp + (size_t)8 * N + 4);
        }
        cp_async_commit();
    };

    issue_stage(0);
    issue_stage(1);
    issue_stage(2);

    for (int s = 0; s < nstages; s++) {
        cp_async_wait2();                // stage s resident
        __syncthreads();                 // copies visible; prev stage consumed
        issue_stage(s + 3);

        const int st = s & 3;
        const float* Ast = Asm + st * 128 * GA_ST;
        const float* Bst = Bsm + st * 16 * GB_ST;

#pragma unroll
        for (int ks = 0; ks < 2; ks++) {
            const int kc = ks * 8 + la3;
            uint32_t af[4][4], bf[8][2];
#pragma unroll
            for (int mt = 0; mt < 4; mt++) {
                const int m = wm * 64 + mt * 16 + lr;
                af[mt][0] = f2tf32(Ast[m * GA_ST + kc]);
                af[mt][1] = f2tf32(Ast[(m + 8) * GA_ST + kc]);
                af[mt][2] = f2tf32(Ast[m * GA_ST + kc + 4]);
                af[mt][3] = f2tf32(Ast[(m + 8) * GA_ST + kc + 4]);
            }
#pragma unroll
            for (int nt = 0; nt < 8; nt++) {
                const int n = wn * 64 + nt * 8 + lr;
                bf[nt][0] = f2tf32(Bst[kc * GB_ST + n]);
                bf[nt][1] = f2tf32(Bst[(kc + 4) * GB_ST + n]);
            }
#pragma unroll
            for (int mt = 0; mt < 4; mt++)
#pragma unroll
                for (int nt = 0; nt < 8; nt++)
                    mma_tf32(acc[mt][nt], af[mt], bf[nt]);
        }
    }

    // ---- epilogue: bias (+ReLU), float2 stores ----
#pragma unroll
    for (int mt = 0; mt < 4; mt++) {
        const int r = rowBase + wm * 64 + mt * 16 + lr;
#pragma unroll
        for (int nt = 0; nt < 8; nt++) {
            const int cc = colBase + wn * 64 + nt * 8 + la3 * 2;
            const float2 bb = *(const float2*)(bias + cc);
            float2 o0, o1;
            o0.x = acc[mt][nt][0] + bb.x;
            o0.y = acc[mt][nt][1] + bb.y;
            o1.x = acc[mt][nt][2] + bb.x;
            o1.y = acc[mt][nt][3] + bb.y;
            if (RELU) {
                o0.x = fmaxf(o0.x, 0.f); o0.y = fmaxf(o0.y, 0.f);
                o1.x = fmaxf(o1.x, 0.f); o1.y = fmaxf(o1.y, 0.f);
            }
            *(float2*)(C + (size_t)r * N + cc)       = o0;
            *(float2*)(C + (size_t)(r + 8) * N + cc) = o1;
        }
    }
}

// ---------------- Tensor-core flash attention (unchanged from R12) ---------
#define AQ2  256
#define PST2 268
#define KRST 68
#define VRST 72
#define QSG2 68
#define OFF2_PS    65536
#define OFF2_KIMG  (OFF2_PS + 64 * PST2 * 4)
#define OFF2_VIMG  (OFF2_KIMG + 16384)
#define OFF2_KRAW  (OFF2_VIMG + 16384)
#define OFF2_VRAW  (OFF2_KRAW + 64 * KRST * 4)
#define ATT3_SMEM  (OFF2_VRAW + 64 * VRST * 4)

#define QSCALE 0.1803368801111204f

__global__ __launch_bounds__(256, 1) void attention_tc_kernel(
    const float* __restrict__ Q, const float* __restrict__ K,
    const float* __restrict__ V, float* __restrict__ O)
{
    extern __shared__ char asmem[];
    uint4*    Qimg = (uint4*)asmem;
    uint32_t* Ps   = (uint32_t*)(asmem + OFF2_PS);
    float*    Qstg = (float*)(asmem + OFF2_PS);
    uint2*    Kimg = (uint2*)(asmem + OFF2_KIMG);
    uint2*    Vimg = (uint2*)(asmem + OFF2_VIMG);
    float*    Kraw = (float*)(asmem + OFF2_KRAW);
    float*    Vraw = (float*)(asmem + OFF2_VRAW);

    const int tid  = threadIdx.x;
    const int lane = tid & 31;
    const int warp = tid >> 5;
    const int la3  = lane & 3;
    const int lr   = lane >> 2;
    const int qb = blockIdx.x, h = blockIdx.y, b = blockIdx.z;

    const float* Qg = Q + ((size_t)(b * SEQLEN) + qb * AQ2) * D_MODEL + h * HEAD_DIM;
    const float* Kg = K + (size_t)(b * SEQLEN) * D_MODEL + h * HEAD_DIM;
    const float* Vg = V + (size_t)(b * SEQLEN) * D_MODEL + h * HEAD_DIM;

    const uint32_t kraw_base = (uint32_t)__cvta_generic_to_shared(Kraw);
    const uint32_t vraw_base = (uint32_t)__cvta_generic_to_shared(Vraw);

#pragma unroll
    for (int i = 0; i < 4; i++) {
        int f = tid + i * 256, r = f >> 4, d4 = (f & 15) << 2;
        cp_async16(kraw_base + (r * KRST + d4) * 4, Kg + (size_t)r * D_MODEL + d4);
        cp_async16(vraw_base + (r * VRST + d4) * 4, Vg + (size_t)r * D_MODEL + d4);
    }
    cp_async_commit();

#pragma unroll
    for (int pass = 0; pass < 2; pass++) {
        if (pass) __syncthreads();
#pragma unroll
        for (int i = 0; i < 8; i++) {
            int f = tid + i * 256;
            int r = f >> 4, d4 = (f & 15) << 2;
            float4 qv = *(const float4*)(Qg + (size_t)(pass * 128 + r) * D_MODEL + d4);
            Qstg[r * QSG2 + d4 + 0] = qv.x * QSCALE;
            Qstg[r * QSG2 + d4 + 1] = qv.y * QSCALE;
            Qstg[r * QSG2 + d4 + 2] = qv.z * QSCALE;
            Qstg[r * QSG2 + d4 + 3] = qv.w * QSCALE;
        }
        __syncthreads();
        if ((warp >> 2) == pass) {
            const int rloc = (warp & 3) * 32 + lr;
#pragma unroll
            for (int mt = 0; mt < 2; mt++) {
                const int rm = rloc + mt * 16;
#pragma unroll
                for (int ks = 0; ks < 8; ks++) {
                    uint4 af;
                    af.x = f2tf32(Qstg[rm * QSG2 + ks * 8 + la3]);
                    af.y = f2tf32(Qstg[(rm + 8) * QSG2 + ks * 8 + la3]);
                    af.z = f2tf32(Qstg[rm * QSG2 + ks * 8 + la3 + 4]);
                    af.w = f2tf32(Qstg[(rm + 8) * QSG2 + ks * 8 + la3 + 4]);
                    Qimg[((warp * 2 + mt) * 8 + ks) * 32 + lane] = af;
                }
            }
        }
    }

    float mrow[4], lrow[4];
#pragma unroll
    for (int g = 0; g < 4; g++) { mrow[g] = -1e30f; lrow[g] = 0.f; }
    float acc[2][8][4];
#pragma unroll
    for (int mt = 0; mt < 2; mt++)
#pragma unroll
        for (int nt = 0; nt < 8; nt++)
#pragma unroll
            for (int r = 0; r < 4; r++) acc[mt][nt][r] = 0.f;

    const int r0 = warp * 32 + lr;

    for (int kb = 0; kb < SEQLEN / 64; kb++) {
        cp_async_wait0();
        __syncthreads();

#pragma unroll
        for (int j = 0; j < 8; j++) {
            const int idx = warp * 8 + j;
            const int ks = idx >> 3, nt = idx & 7;
            float k0 = Kraw[(nt * 8 + lr) * KRST + ks * 8 + la3];
            float k1 = Kraw[(nt * 8 + lr) * KRST + ks * 8 + la3 + 4];
            float v0 = Vraw[(ks * 8 + la3) * VRST + nt * 8 + lr];
            float v1 = Vraw[(ks * 8 + la3 + 4) * VRST + nt * 8 + lr];
            uint2 kk2 = {f2tf32(k0), f2tf32(k1)};
            uint2 vv2 = {f2tf32(v0), f2tf32(v1)};
            Kimg[idx * 32 + lane] = kk2;
            Vimg[idx * 32 + lane] = vv2;
        }
        __syncthreads();

        if (kb + 1 < SEQLEN / 64) {
            const size_t tb = (size_t)((kb + 1) * 64) * D_MODEL;
#pragma unroll
            for (int i = 0; i < 4; i++) {
                int f = tid + i * 256, r = f >> 4, d4 = (f & 15) << 2;
                cp_async16(kraw_base + (r * KRST + d4) * 4, Kg + tb + (size_t)r * D_MODEL + d4);
                cp_async16(vraw_base + (r * VRST + d4) * 4, Vg + tb + (size_t)r * D_MODEL + d4);
            }
            cp_async_commit();
        }

        float c[2][8][4];
#pragma unroll
        for (int mt = 0; mt < 2; mt++)
#pragma unroll
            for (int nt = 0; nt < 8; nt++)
#pragma unroll
                for (int r = 0; r < 4; r++) c[mt][nt][r] = 0.f;

#pragma unroll
        for (int ks = 0; ks < 8; ks++) {
            uint4 a0v = Qimg[((warp * 2 + 0) * 8 + ks) * 32 + lane];
            uint4 a1v = Qimg[((warp * 2 + 1) * 8 + ks) * 32 + lane];
            uint32_t a0[4] = {a0v.x, a0v.y, a0v.z, a0v.w};
            uint32_t a1[4] = {a1v.x, a1v.y, a1v.z, a1v.w};
#pragma unroll
            for (int nt = 0; nt < 8; nt++) {
                uint2 bf2 = Kimg[(ks * 8 + nt) * 32 + lane];
                uint32_t bf[2] = {bf2.x, bf2.y};
                mma_tf32(c[0][nt], a0, bf);
                mma_tf32(c[1][nt], a1, bf);
            }
        }

#pragma unroll
        for (int mt = 0; mt < 2; mt++) {
            float mx0 = -1e30f, mx1 = -1e30f;
#pragma unroll
            for (int nt = 0; nt < 8; nt++) {
                mx0 = fmaxf(mx0, fmaxf(c[mt][nt][0], c[mt][nt][1]));
                mx1 = fmaxf(mx1, fmaxf(c[mt][nt][2], c[mt][nt][3]));
            }
            mx0 = fmaxf(mx0, __shfl_xor_sync(0xffffffffu, mx0, 1));
            mx0 = fmaxf(mx0, __shfl_xor_sync(0xffffffffu, mx0, 2));
            mx1 = fmaxf(mx1, __shfl_xor_sync(0xffffffffu, mx1, 1));
            mx1 = fmaxf(mx1, __shfl_xor_sync(0xffffffffu, mx1, 2));
            const int g0 = mt * 2, g1 = mt * 2 + 1;
            const float mn0 = fmaxf(mrow[g0], mx0);
            const float mn1 = fmaxf(mrow[g1], mx1);
            const float al0 = ex2f(mrow[g0] - mn0);
            const float al1 = ex2f(mrow[g1] - mn1);
            float s0 = 0.f, s1 = 0.f;
#pragma unroll
            for (int nt = 0; nt < 8; nt++) {
                c[mt][nt][0] = ex2f(c[mt][nt][0] - mn0);
                c[mt][nt][1] = ex2f(c[mt][nt][1] - mn0);
                c[mt][nt][2] = ex2f(c[mt][nt][2] - mn1);
                c[mt][nt][3] = ex2f(c[mt][nt][3] - mn1);
                s0 += c[mt][nt][0] + c[mt][nt][1];
                s1 += c[mt][nt][2] + c[mt][nt][3];
            }
            s0 += __shfl_xor_sync(0xffffffffu, s0, 1);
            s0 += __shfl_xor_sync(0xffffffffu, s0, 2);
            s1 += __shfl_xor_sync(0xffffffffu, s1, 1);
            s1 += __shfl_xor_sync(0xffffffffu, s1, 2);
            lrow[g0] = lrow[g0] * al0 + s0; mrow[g0] = mn0;
            lrow[g1] = lrow[g1] * al1 + s1; mrow[g1] = mn1;
#pragma unroll
            for (int nt = 0; nt < 8; nt++) {
                acc[mt][nt][0] *= al0; acc[mt][nt][1] *= al0;
                acc[mt][nt][2] *= al1; acc[mt][nt][3] *= al1;
            }
        }

        __syncwarp();
#pragma unroll
        for (int mt = 0; mt < 2; mt++) {
            const int rm = r0 + mt * 16;
#pragma unroll
            for (int nt = 0; nt < 8; nt++) {
                const int k0 = nt * 8 + la3 * 2;
                Ps[k0 * PST2 + rm]           = f2tf32(c[mt][nt][0]);
                Ps[(k0 + 1) * PST2 + rm]     = f2tf32(c[mt][nt][1]);
                Ps[k0 * PST2 + rm + 8]       = f2tf32(c[mt][nt][2]);
                Ps[(k0 + 1) * PST2 + rm + 8] = f2tf32(c[mt][nt][3]);
            }
        }
        __syncwarp();

#pragma unroll
        for (int ks = 0; ks < 8; ks++) {
            const int kk = ks * 8 + la3;
            uint32_t a0[4], a1[4];
            a0[0] = Ps[kk * PST2 + r0];
            a0[1] = Ps[kk * PST2 + r0 + 8];
            a0[2] = Ps[(kk + 4) * PST2 + r0];
            a0[3] = Ps[(kk + 4) * PST2 + r0 + 8];
            a1[0] = Ps[kk * PST2 + r0 + 16];
            a1[1] = Ps[kk * PST2 + r0 + 24];
            a1[2] = Ps[(kk + 4) * PST2 + r0 + 16];
            a1[3] = Ps[(kk + 4) * PST2 + r0 + 24];
#pragma unroll
            for (int nt = 0; nt < 8; nt++) {
                uint2 bf2 = Vimg[(ks * 8 + nt) * 32 + lane];
                uint32_t bf[2] = {bf2.x, bf2.y};
                mma_tf32(acc[0][nt], a0, bf);
                mma_tf32(acc[1][nt], a1, bf);
            }
        }
    }

#pragma unroll
    for (int mt = 0; mt < 2; mt++) {
        const float inv0 = 1.f / lrow[mt * 2];
        const float inv1 = 1.f / lrow[mt * 2 + 1];
        float* Og = O + ((size_t)(b * SEQLEN) + qb * AQ2 + r0 + mt * 16) * D_MODEL
                      + h * HEAD_DIM;
#pragma unroll
        for (int nt = 0; nt < 8; nt++) {
            const int cc = nt * 8 + la3 * 2;
            float2 o0 = {acc[mt][nt][0] * inv0, acc[mt][nt][1] * inv0};
            float2 o1 = {acc[mt][nt][2] * inv1, acc[mt][nt][3] * inv1};
            *(float2*)(Og + cc)               = o0;
            *(float2*)(Og + 8 * D_MODEL + cc) = o1;
        }
    }
}

// ---------------- add + LayerNorm ------------------------------------------
__global__ __launch_bounds__(256) void add_ln_kernel(
    const float* __restrict__ A, const float* __restrict__ Hh,
    const float* __restrict__ G, const float* __restrict__ Bt,
    float* __restrict__ Out)
{
    const int row = blockIdx.x;
    const int t = threadIdx.x;
    const size_t base = (size_t)row * D_MODEL + t * 4;
    float4 x = *(const float4*)(A + base);
    float4 y = *(const float4*)(Hh + base);
    float4 v = {x.x + y.x, x.y + y.y, x.z + y.z, x.w + y.w};
    float s  = v.x + v.y + v.z + v.w;
    float s2 = v.x * v.x + v.y * v.y + v.z * v.z + v.w * v.w;
#pragma unroll
    for (int o = 16; o; o >>= 1) {
        s  += __shfl_xor_sync(0xffffffffu, s, o);
        s2 += __shfl_xor_sync(0xffffffffu, s2, o);
    }
    __shared__ float sh[16];
    __shared__ float stats[2];
    const int w = t >> 5;
    if ((t & 31) == 0) { sh[w] = s; sh[8 + w] = s2; }
    __syncthreads();
    if (t == 0) {
        float S = 0.f, S2 = 0.f;
        for (int i = 0; i < 8; i++) { S += sh[i]; S2 += sh[8 + i]; }
        float mu = S * (1.f / D_MODEL);
        float var = S2 * (1.f / D_MODEL) - mu * mu;
        stats[0] = mu;
        stats[1] = rsqrtf(var + 1e-5f);
    }
    __syncthreads();
    const float mu = stats[0], r = stats[1];
    float4 g4 = *(const float4*)(G + t * 4);
    float4 b4 = *(const float4*)(Bt + t * 4);
    float4 o;
    o.x = (v.x - mu) * r * g4.x + b4.x;
    o.y = (v.y - mu) * r * g4.y + b4.y;
    o.z = (v.z - mu) * r * g4.z + b4.z;
    o.w = (v.w - mu) * r * g4.w + b4.w;
    *(float4*)(Out + base) = o;
}

// ---------------- launch ---------------------------------------------------
extern "C" void kernel_launch(void* const* d_in, const int* in_sizes, int n_in,
                              void* d_out, int out_size)
{
    const float* hid   = (const float*)d_in[0];
    const float* enc   = (const float*)d_in[1];
    const float* sa_wq = (const float*)d_in[2];
    const float* sa_bq = (const float*)d_in[3];
    const float* sa_wk = (const float*)d_in[4];
    const float* sa_bk = (const float*)d_in[5];
    const float* sa_wv = (const float*)d_in[6];
    const float* sa_bv = (const float*)d_in[7];
    const float* ln1_g = (const float*)d_in[8];
    const float* ln1_b = (const float*)d_in[9];
    const float* ca_wq = (const float*)d_in[10];
    const float* ca_bq = (const float*)d_in[11];
    const float* ca_wk = (const float*)d_in[12];
    const float* ca_bk = (const float*)d_in[13];
    const float* ca_wv = (const float*)d_in[14];
    const float* ca_bv = (const float*)d_in[15];
    const float* ln2_g = (const float*)d_in[16];
    const float* ln2_b = (const float*)d_in[17];
    const float* fc1_w = (const float*)d_in[18];
    const float* fc1_b = (const float*)d_in[19];
    const float* fc2_w = (const float*)d_in[20];
    const float* fc2_b = (const float*)d_in[21];
    const float* ln3_g = (const float*)d_in[22];
    const float* ln3_b = (const float*)d_in[23];

    float *q, *k, *v, *ctx, *x1, *x2, *ffn;
    cudaGetSymbolAddress((void**)&q,   g_q);
    cudaGetSymbolAddress((void**)&k,   g_k);
    cudaGetSymbolAddress((void**)&v,   g_v);
    cudaGetSymbolAddress((void**)&ctx, g_ctx);
    cudaGetSymbolAddress((void**)&x1,  g_x1);
    cudaGetSymbolAddress((void**)&x2,  g_x2);
    cudaGetSymbolAddress((void**)&ffn, g_ffn);

    cudaFuncSetAttribute(attention_tc_kernel,
                         cudaFuncAttributeMaxDynamicSharedMemorySize, ATT3_SMEM);
    cudaFuncSetAttribute(gemm_cp_kernel<0>,
                         cudaFuncAttributeMaxDynamicSharedMemorySize, GEMM_SMEM);
    cudaFuncSetAttribute(gemm_cp_kernel<1>,
                         cudaFuncAttributeMaxDynamicSharedMemorySize, GEMM_SMEM);

    const dim3 att_grid(SEQLEN / AQ2, N_HEADS, BATCH);

    // ---- self-attention: fused QKV projection (one launch) ----
    gemm_cp_kernel<0><<<dim3(24, 32), 128, GEMM_SMEM>>>(
        hid, sa_wq, sa_bq, q,
        hid, sa_wk, sa_bk, k,
        hid, sa_wv, sa_bv, v,
        NTOK, D_MODEL, D_MODEL, 8);
    attention_tc_kernel<<<att_grid, 256, ATT3_SMEM>>>(q, k, v, ctx);
    add_ln_kernel<<<NTOK, 256>>>(hid, ctx, ln1_g, ln1_b, x1);

    // ---- cross-attention: fused Q(from x1), K,V(from enc) in one launch ----
    gemm_cp_kernel<0><<<dim3(24, 32), 128, GEMM_SMEM>>>(
        x1,  ca_wq, ca_bq, q,
        enc, ca_wk, ca_bk, k,
        enc, ca_wv, ca_bv, v,
        NTOK, D_MODEL, D_MODEL, 8);
    attention_tc_kernel<<<att_grid, 256, ATT3_SMEM>>>(q, k, v, ctx);
    add_ln_kernel<<<NTOK, 256>>>(x1, ctx, ln2_g, ln2_b, x2);

    // ---- feed-forward ----
    gemm_cp_kernel<1><<<dim3(32, 32), 128, GEMM_SMEM>>>(
        x2, fc1_w, fc1_b, ffn,
        x2, fc1_w, fc1_b, ffn,
        x2, fc1_w, fc1_b, ffn,
        NTOK, FFN_DIM, D_MODEL, 32);
    gemm_cp_kernel<0><<<dim3(8, 32), 128, GEMM_SMEM>>>(
        ffn, fc2_w, fc2_b, ctx,
        ffn, fc2_w, fc2_b, ctx,
        ffn, fc2_w, fc2_b, ctx,
        NTOK, D_MODEL, FFN_DIM, 8);
    add_ln_kernel<<<NTOK, 256>>>(x2, ctx, ln3_g, ln3_b, (float*)d_out);
}

// round 17
// speedup vs baseline: 1.1156x; 1.1156x over previous
#include <cuda_runtime.h>
#include <stdint.h>

#define D_MODEL 1024
#define FFN_DIM 4096
#define N_HEADS 16
#define HEAD_DIM 64
#define SEQLEN 2048
#define BATCH 2
#define NTOK (BATCH * SEQLEN)

// ---------------- scratch (device globals: no runtime allocation) ----------
__device__ float g_q[NTOK * D_MODEL];
__device__ float g_k[NTOK * D_MODEL];
__device__ float g_v[NTOK * D_MODEL];
__device__ float g_ctx[NTOK * D_MODEL];
__device__ float g_x1[NTOK * D_MODEL];
__device__ float g_x2[NTOK * D_MODEL];
__device__ float g_ffn[(size_t)NTOK * FFN_DIM];

// ---------------- tf32 helpers ---------------------------------------------
__device__ __forceinline__ uint32_t f2tf32(float x) {
    uint32_t r;
    asm("cvt.rna.tf32.f32 %0, %1;" : "=r"(r) : "f"(x));
    return r;
}

__device__ __forceinline__ float ex2f(float x) {
    float r;
    asm("ex2.approx.ftz.f32 %0, %1;" : "=f"(r) : "f"(x));
    return r;
}

__device__ __forceinline__ void mma_tf32(
    float* c, const uint32_t* a, const uint32_t* b)
{
    asm volatile(
        "mma.sync.aligned.m16n8k8.row.col.f32.tf32.tf32.f32 "
        "{%0,%1,%2,%3}, {%4,%5,%6,%7}, {%8,%9}, {%0,%1,%2,%3};\n"
        : "+f"(c[0]), "+f"(c[1]), "+f"(c[2]), "+f"(c[3])
        : "r"(a[0]), "r"(a[1]), "r"(a[2]), "r"(a[3]),
          "r"(b[0]), "r"(b[1]));
}

__device__ __forceinline__ void cp_async16(uint32_t dst_smem, const void* src) {
    asm volatile("cp.async.ca.shared.global [%0], [%1], 16;"
                 :: "r"(dst_smem), "l"(src));
}
__device__ __forceinline__ void cp_async_commit() {
    asm volatile("cp.async.commit_group;");
}
__device__ __forceinline__ void cp_async_wait0() {
    asm volatile("cp.async.wait_group 0;" ::: "memory");
}

// ---------------- GEMM: 128x128 tile, BK=32, 2-stage cp.async --------------
// C[M,Nper] = A[M,K] @ W[K,Nper] + bias (opt ReLU), up to 3 (A,W,bias,C)
// tuples per launch. 256 threads = 8 warps as 2m x 4n; warp tile 64x32
// (R12's proven shape: 16 warps/SM). BK=32 -> 4 k-groups per barrier,
// halving barrier count vs R12. smem: A [2][128][36], B [2][32][136].
#define GA_ST 36
#define GB_ST 136
#define GEMM_SMEM ((2 * 128 * GA_ST + 2 * 32 * GB_ST) * 4)   // 71680 B

template <int RELU>
__global__ __launch_bounds__(256, 2) void gemm_cp_kernel(
    const float* __restrict__ A0, const float* __restrict__ W0,
    const float* __restrict__ bias0, float* __restrict__ C0,
    const float* __restrict__ A1, const float* __restrict__ W1,
    const float* __restrict__ bias1, float* __restrict__ C1,
    const float* __restrict__ A2, const float* __restrict__ W2,
    const float* __restrict__ bias2, float* __restrict__ C2,
    int M, int N, int K, int bpm)
{
    extern __shared__ float gsm[];
    float* Asm = gsm;                    // [2][128][GA_ST]
    float* Bsm = gsm + 2 * 128 * GA_ST;  // [2][32][GB_ST]

    const int tid  = threadIdx.x;
    const int lane = tid & 31;
    const int warp = tid >> 5;
    const int wm = warp >> 2, wn = warp & 3;     // 2m x 4n (warp tile 64x32)
    const int la3 = lane & 3, lr = lane >> 2;
    const int mat = blockIdx.x / bpm;
    const int colBase = (blockIdx.x % bpm) * 128;
    const int rowBase = blockIdx.y * 128;

    const float* A    = (mat == 0) ? A0    : (mat == 1) ? A1    : A2;
    const float* W    = (mat == 0) ? W0    : (mat == 1) ? W1    : W2;
    const float* bias = (mat == 0) ? bias0 : (mat == 1) ? bias1 : bias2;
    float*       C    = (mat == 0) ? C0    : (mat == 1) ? C1    : C2;

    const uint32_t a_base = (uint32_t)__cvta_generic_to_shared(Asm);
    const uint32_t b_base = (uint32_t)__cvta_generic_to_shared(Bsm);

    // loaders (256 threads), 32-k stage:
    // A: thread owns row tid>>1, k-base (tid&1)*16, 4 chunks of 4 floats.
    // B: thread owns rows (tid>>4) and (tid>>4)+16, 8 cols at (tid&15)*8.
    const int aRow = tid >> 1;
    const int aKc  = (tid & 1) * 16;
    const int bK   = tid >> 4;             // 0..15
    const int bN8  = (tid & 15) * 8;       // 0..120

    const float* Abase = A + (size_t)(rowBase + aRow) * K + aKc;
    const float* Wbase = W + (size_t)bK * N + colBase + bN8;

    float acc[4][4][4];
#pragma unroll
    for (int i = 0; i < 4; i++)
#pragma unroll
        for (int j = 0; j < 4; j++)
#pragma unroll
            for (int r = 0; r < 4; r++) acc[i][j][r] = 0.f;

    const int nstages = K / 32;

    auto issue_stage = [&](int s) {
        if (s < nstages) {
            const int k0 = s * 32;
            const int st = s & 1;
            const float* Ap = Abase + k0;
            const uint32_t abuf = a_base + (uint32_t)(((st * 128 + aRow) * GA_ST + aKc) * 4);
            cp_async16(abuf,      Ap);
            cp_async16(abuf + 16, Ap + 4);
            cp_async16(abuf + 32, Ap + 8);
            cp_async16(abuf + 48, Ap + 12);
            const float* Wp = Wbase + (size_t)k0 * N;
            const uint32_t bbuf0 = b_base + (uint32_t)((((st * 32 + bK) * GB_ST) + bN8) * 4);
            const uint32_t bbuf1 = b_base + (uint32_t)((((st * 32 + bK + 16) * GB_ST) + bN8) * 4);
            cp_async16(bbuf0,      Wp);
            cp_async16(bbuf0 + 16, Wp + 4);
            cp_async16(bbuf1,      Wp + (size_t)16 * N);
            cp_async16(bbuf1 + 16, Wp + (size_t)16 * N + 4);
        }
        cp_async_commit();
    };

    issue_stage(0);

    for (int s = 0; s < nstages; s++) {
        cp_async_wait0();                // stage s resident (s+1 not yet issued)
        __syncthreads();                 // visible to all; prev stage consumed
        issue_stage(s + 1);              // DMA overlaps compute below

        const int st = s & 1;
        const float* Ast = Asm + st * 128 * GA_ST;
        const float* Bst = Bsm + st * 32 * GB_ST;

#pragma unroll
        for (int ks = 0; ks < 4; ks++) {
            const int kc = ks * 8 + la3;
            uint32_t af[4][4], bf[4][2];
#pragma unroll
            for (int mt = 0; mt < 4; mt++) {
                const int m = wm * 64 + mt * 16 + lr;
                af[mt][0] = f2tf32(Ast[m * GA_ST + kc]);
                af[mt][1] = f2tf32(Ast[(m + 8) * GA_ST + kc]);
                af[mt][2] = f2tf32(Ast[m * GA_ST + kc + 4]);
                af[mt][3] = f2tf32(Ast[(m + 8) * GA_ST + kc + 4]);
            }
#pragma unroll
            for (int nt = 0; nt < 4; nt++) {
                const int n = wn * 32 + nt * 8 + lr;
                bf[nt][0] = f2tf32(Bst[kc * GB_ST + n]);
                bf[nt][1] = f2tf32(Bst[(kc + 4) * GB_ST + n]);
            }
#pragma unroll
            for (int mt = 0; mt < 4; mt++)
#pragma unroll
                for (int nt = 0; nt < 4; nt++)
                    mma_tf32(acc[mt][nt], af[mt], bf[nt]);
        }
    }

    // ---- epilogue: bias (+ReLU), float2 stores ----
#pragma unroll
    for (int mt = 0; mt < 4; mt++) {
        const int r = rowBase + wm * 64 + mt * 16 + lr;
#pragma unroll
        for (int nt = 0; nt < 4; nt++) {
            const int cc = colBase + wn * 32 + nt * 8 + la3 * 2;
            const float2 bb = *(const float2*)(bias + cc);
            float2 o0, o1;
            o0.x = acc[mt][nt][0] + bb.x;
            o0.y = acc[mt][nt][1] + bb.y;
            o1.x = acc[mt][nt][2] + bb.x;
            o1.y = acc[mt][nt][3] + bb.y;
            if (RELU) {
                o0.x = fmaxf(o0.x, 0.f); o0.y = fmaxf(o0.y, 0.f);
                o1.x = fmaxf(o1.x, 0.f); o1.y = fmaxf(o1.y, 0.f);
            }
            *(float2*)(C + (size_t)r * N + cc)       = o0;
            *(float2*)(C + (size_t)(r + 8) * N + cc) = o1;
        }
    }
}

// ---------------- Tensor-core flash attention (unchanged from R12) ---------
#define AQ2  256
#define PST2 268
#define KRST 68
#define VRST 72
#define QSG2 68
#define OFF2_PS    65536
#define OFF2_KIMG  (OFF2_PS + 64 * PST2 * 4)
#define OFF2_VIMG  (OFF2_KIMG + 16384)
#define OFF2_KRAW  (OFF2_VIMG + 16384)
#define OFF2_VRAW  (OFF2_KRAW + 64 * KRST * 4)
#define ATT3_SMEM  (OFF2_VRAW + 64 * VRST * 4)

#define QSCALE 0.1803368801111204f

__global__ __launch_bounds__(256, 1) void attention_tc_kernel(
    const float* __restrict__ Q, const float* __restrict__ K,
    const float* __restrict__ V, float* __restrict__ O)
{
    extern __shared__ char asmem[];
    uint4*    Qimg = (uint4*)asmem;
    uint32_t* Ps   = (uint32_t*)(asmem + OFF2_PS);
    float*    Qstg = (float*)(asmem + OFF2_PS);
    uint2*    Kimg = (uint2*)(asmem + OFF2_KIMG);
    uint2*    Vimg = (uint2*)(asmem + OFF2_VIMG);
    float*    Kraw = (float*)(asmem + OFF2_KRAW);
    float*    Vraw = (float*)(asmem + OFF2_VRAW);

    const int tid  = threadIdx.x;
    const int lane = tid & 31;
    const int warp = tid >> 5;
    const int la3  = lane & 3;
    const int lr   = lane >> 2;
    const int qb = blockIdx.x, h = blockIdx.y, b = blockIdx.z;

    const float* Qg = Q + ((size_t)(b * SEQLEN) + qb * AQ2) * D_MODEL + h * HEAD_DIM;
    const float* Kg = K + (size_t)(b * SEQLEN) * D_MODEL + h * HEAD_DIM;
    const float* Vg = V + (size_t)(b * SEQLEN) * D_MODEL + h * HEAD_DIM;

    const uint32_t kraw_base = (uint32_t)__cvta_generic_to_shared(Kraw);
    const uint32_t vraw_base = (uint32_t)__cvta_generic_to_shared(Vraw);

#pragma unroll
    for (int i = 0; i < 4; i++) {
        int f = tid + i * 256, r = f >> 4, d4 = (f & 15) << 2;
        cp_async16(kraw_base + (r * KRST + d4) * 4, Kg + (size_t)r * D_MODEL + d4);
        cp_async16(vraw_base + (r * VRST + d4) * 4, Vg + (size_t)r * D_MODEL + d4);
    }
    cp_async_commit();

#pragma unroll
    for (int pass = 0; pass < 2; pass++) {
        if (pass) __syncthreads();
#pragma unroll
        for (int i = 0; i < 8; i++) {
            int f = tid + i * 256;
            int r = f >> 4, d4 = (f & 15) << 2;
            float4 qv = *(const float4*)(Qg + (size_t)(pass * 128 + r) * D_MODEL + d4);
            Qstg[r * QSG2 + d4 + 0] = qv.x * QSCALE;
            Qstg[r * QSG2 + d4 + 1] = qv.y * QSCALE;
            Qstg[r * QSG2 + d4 + 2] = qv.z * QSCALE;
            Qstg[r * QSG2 + d4 + 3] = qv.w * QSCALE;
        }
        __syncthreads();
        if ((warp >> 2) == pass) {
            const int rloc = (warp & 3) * 32 + lr;
#pragma unroll
            for (int mt = 0; mt < 2; mt++) {
                const int rm = rloc + mt * 16;
#pragma unroll
                for (int ks = 0; ks < 8; ks++) {
                    uint4 af;
                    af.x = f2tf32(Qstg[rm * QSG2 + ks * 8 + la3]);
                    af.y = f2tf32(Qstg[(rm + 8) * QSG2 + ks * 8 + la3]);
                    af.z = f2tf32(Qstg[rm * QSG2 + ks * 8 + la3 + 4]);
                    af.w = f2tf32(Qstg[(rm + 8) * QSG2 + ks * 8 + la3 + 4]);
                    Qimg[((warp * 2 + mt) * 8 + ks) * 32 + lane] = af;
                }
            }
        }
    }

    float mrow[4], lrow[4];
#pragma unroll
    for (int g = 0; g < 4; g++) { mrow[g] = -1e30f; lrow[g] = 0.f; }
    float acc[2][8][4];
#pragma unroll
    for (int mt = 0; mt < 2; mt++)
#pragma unroll
        for (int nt = 0; nt < 8; nt++)
#pragma unroll
            for (int r = 0; r < 4; r++) acc[mt][nt][r] = 0.f;

    const int r0 = warp * 32 + lr;

    for (int kb = 0; kb < SEQLEN / 64; kb++) {
        cp_async_wait0();
        __syncthreads();

#pragma unroll
        for (int j = 0; j < 8; j++) {
            const int idx = warp * 8 + j;
            const int ks = idx >> 3, nt = idx & 7;
            float k0 = Kraw[(nt * 8 + lr) * KRST + ks * 8 + la3];
            float k1 = Kraw[(nt * 8 + lr) * KRST + ks * 8 + la3 + 4];
            float v0 = Vraw[(ks * 8 + la3) * VRST + nt * 8 + lr];
            float v1 = Vraw[(ks * 8 + la3 + 4) * VRST + nt * 8 + lr];
            uint2 kk2 = {f2tf32(k0), f2tf32(k1)};
            uint2 vv2 = {f2tf32(v0), f2tf32(v1)};
            Kimg[idx * 32 + lane] = kk2;
            Vimg[idx * 32 + lane] = vv2;
        }
        __syncthreads();

        if (kb + 1 < SEQLEN / 64) {
            const size_t tb = (size_t)((kb + 1) * 64) * D_MODEL;
#pragma unroll
            for (int i = 0; i < 4; i++) {
                int f = tid + i * 256, r = f >> 4, d4 = (f & 15) << 2;
                cp_async16(kraw_base + (r * KRST + d4) * 4, Kg + tb + (size_t)r * D_MODEL + d4);
                cp_async16(vraw_base + (r * VRST + d4) * 4, Vg + tb + (size_t)r * D_MODEL + d4);
            }
            cp_async_commit();
        }

        float c[2][8][4];
#pragma unroll
        for (int mt = 0; mt < 2; mt++)
#pragma unroll
            for (int nt = 0; nt < 8; nt++)
#pragma unroll
                for (int r = 0; r < 4; r++) c[mt][nt][r] = 0.f;

#pragma unroll
        for (int ks = 0; ks < 8; ks++) {
            uint4 a0v = Qimg[((warp * 2 + 0) * 8 + ks) * 32 + lane];
            uint4 a1v = Qimg[((warp * 2 + 1) * 8 + ks) * 32 + lane];
            uint32_t a0[4] = {a0v.x, a0v.y, a0v.z, a0v.w};
            uint32_t a1[4] = {a1v.x, a1v.y, a1v.z, a1v.w};
#pragma unroll
            for (int nt = 0; nt < 8; nt++) {
                uint2 bf2 = Kimg[(ks * 8 + nt) * 32 + lane];
                uint32_t bf[2] = {bf2.x, bf2.y};
                mma_tf32(c[0][nt], a0, bf);
                mma_tf32(c[1][nt], a1, bf);
            }
        }

#pragma unroll
        for (int mt = 0; mt < 2; mt++) {
            float mx0 = -1e30f, mx1 = -1e30f;
#pragma unroll
            for (int nt = 0; nt < 8; nt++) {
                mx0 = fmaxf(mx0, fmaxf(c[mt][nt][0], c[mt][nt][1]));
                mx1 = fmaxf(mx1, fmaxf(c[mt][nt][2], c[mt][nt][3]));
            }
            mx0 = fmaxf(mx0, __shfl_xor_sync(0xffffffffu, mx0, 1));
            mx0 = fmaxf(mx0, __shfl_xor_sync(0xffffffffu, mx0, 2));
            mx1 = fmaxf(mx1, __shfl_xor_sync(0xffffffffu, mx1, 1));
            mx1 = fmaxf(mx1, __shfl_xor_sync(0xffffffffu, mx1, 2));
            const int g0 = mt * 2, g1 = mt * 2 + 1;
            const float mn0 = fmaxf(mrow[g0], mx0);
            const float mn1 = fmaxf(mrow[g1], mx1);
            const float al0 = ex2f(mrow[g0] - mn0);
            const float al1 = ex2f(mrow[g1] - mn1);
            float s0 = 0.f, s1 = 0.f;
#pragma unroll
            for (int nt = 0; nt < 8; nt++) {
                c[mt][nt][0] = ex2f(c[mt][nt][0] - mn0);
                c[mt][nt][1] = ex2f(c[mt][nt][1] - mn0);
                c[mt][nt][2] = ex2f(c[mt][nt][2] - mn1);
                c[mt][nt][3] = ex2f(c[mt][nt][3] - mn1);
                s0 += c[mt][nt][0] + c[mt][nt][1];
                s1 += c[mt][nt][2] + c[mt][nt][3];
            }
            s0 += __shfl_xor_sync(0xffffffffu, s0, 1);
            s0 += __shfl_xor_sync(0xffffffffu, s0, 2);
            s1 += __shfl_xor_sync(0xffffffffu, s1, 1);
            s1 += __shfl_xor_sync(0xffffffffu, s1, 2);
            lrow[g0] = lrow[g0] * al0 + s0; mrow[g0] = mn0;
            lrow[g1] = lrow[g1] * al1 + s1; mrow[g1] = mn1;
#pragma unroll
            for (int nt = 0; nt < 8; nt++) {
                acc[mt][nt][0] *= al0; acc[mt][nt][1] *= al0;
                acc[mt][nt][2] *= al1; acc[mt][nt][3] *= al1;
            }
        }

        __syncwarp();
#pragma unroll
        for (int mt = 0; mt < 2; mt++) {
            const int rm = r0 + mt * 16;
#pragma unroll
            for (int nt = 0; nt < 8; nt++) {
                const int k0 = nt * 8 + la3 * 2;
                Ps[k0 * PST2 + rm]           = f2tf32(c[mt][nt][0]);
                Ps[(k0 + 1) * PST2 + rm]     = f2tf32(c[mt][nt][1]);
                Ps[k0 * PST2 + rm + 8]       = f2tf32(c[mt][nt][2]);
                Ps[(k0 + 1) * PST2 + rm + 8] = f2tf32(c[mt][nt][3]);
            }
        }
        __syncwarp();

#pragma unroll
        for (int ks = 0; ks < 8; ks++) {
            const int kk = ks * 8 + la3;
            uint32_t a0[4], a1[4];
            a0[0] = Ps[kk * PST2 + r0];
            a0[1] = Ps[kk * PST2 + r0 + 8];
            a0[2] = Ps[(kk + 4) * PST2 + r0];
            a0[3] = Ps[(kk + 4) * PST2 + r0 + 8];
            a1[0] = Ps[kk * PST2 + r0 + 16];
            a1[1] = Ps[kk * PST2 + r0 + 24];
            a1[2] = Ps[(kk + 4) * PST2 + r0 + 16];
            a1[3] = Ps[(kk + 4) * PST2 + r0 + 24];
#pragma unroll
            for (int nt = 0; nt < 8; nt++) {
                uint2 bf2 = Vimg[(ks * 8 + nt) * 32 + lane];
                uint32_t bf[2] = {bf2.x, bf2.y};
                mma_tf32(acc[0][nt], a0, bf);
                mma_tf32(acc[1][nt], a1, bf);
            }
        }
    }

#pragma unroll
    for (int mt = 0; mt < 2; mt++) {
        const float inv0 = 1.f / lrow[mt * 2];
        const float inv1 = 1.f / lrow[mt * 2 + 1];
        float* Og = O + ((size_t)(b * SEQLEN) + qb * AQ2 + r0 + mt * 16) * D_MODEL
                      + h * HEAD_DIM;
#pragma unroll
        for (int nt = 0; nt < 8; nt++) {
            const int cc = nt * 8 + la3 * 2;
            float2 o0 = {acc[mt][nt][0] * inv0, acc[mt][nt][1] * inv0};
            float2 o1 = {acc[mt][nt][2] * inv1, acc[mt][nt][3] * inv1};
            *(float2*)(Og + cc)               = o0;
            *(float2*)(Og + 8 * D_MODEL + cc) = o1;
        }
    }
}

// ---------------- add + LayerNorm ------------------------------------------
__global__ __launch_bounds__(256) void add_ln_kernel(
    const float* __restrict__ A, const float* __restrict__ Hh,
    const float* __restrict__ G, const float* __restrict__ Bt,
    float* __restrict__ Out)
{
    const int row = blockIdx.x;
    const int t = threadIdx.x;
    const size_t base = (size_t)row * D_MODEL + t * 4;
    float4 x = *(const float4*)(A + base);
    float4 y = *(const float4*)(Hh + base);
    float4 v = {x.x + y.x, x.y + y.y, x.z + y.z, x.w + y.w};
    float s  = v.x + v.y + v.z + v.w;
    float s2 = v.x * v.x + v.y * v.y + v.z * v.z + v.w * v.w;
#pragma unroll
    for (int o = 16; o; o >>= 1) {
        s  += __shfl_xor_sync(0xffffffffu, s, o);
        s2 += __shfl_xor_sync(0xffffffffu, s2, o);
    }
    __shared__ float sh[16];
    __shared__ float stats[2];
    const int w = t >> 5;
    if ((t & 31) == 0) { sh[w] = s; sh[8 + w] = s2; }
    __syncthreads();
    if (t == 0) {
        float S = 0.f, S2 = 0.f;
        for (int i = 0; i < 8; i++) { S += sh[i]; S2 += sh[8 + i]; }
        float mu = S * (1.f / D_MODEL);
        float var = S2 * (1.f / D_MODEL) - mu * mu;
        stats[0] = mu;
        stats[1] = rsqrtf(var + 1e-5f);
    }
    __syncthreads();
    const float mu = stats[0], r = stats[1];
    float4 g4 = *(const float4*)(G + t * 4);
    float4 b4 = *(const float4*)(Bt + t * 4);
    float4 o;
    o.x = (v.x - mu) * r * g4.x + b4.x;
    o.y = (v.y - mu) * r * g4.y + b4.y;
    o.z = (v.z - mu) * r * g4.z + b4.z;
    o.w = (v.w - mu) * r * g4.w + b4.w;
    *(float4*)(Out + base) = o;
}

// ---------------- launch ---------------------------------------------------
extern "C" void kernel_launch(void* const* d_in, const int* in_sizes, int n_in,
                              void* d_out, int out_size)
{
    const float* hid   = (const float*)d_in[0];
    const float* enc   = (const float*)d_in[1];
    const float* sa_wq = (const float*)d_in[2];
    const float* sa_bq = (const float*)d_in[3];
    const float* sa_wk = (const float*)d_in[4];
    const float* sa_bk = (const float*)d_in[5];
    const float* sa_wv = (const float*)d_in[6];
    const float* sa_bv = (const float*)d_in[7];
    const float* ln1_g = (const float*)d_in[8];
    const float* ln1_b = (const float*)d_in[9];
    const float* ca_wq = (const float*)d_in[10];
    const float* ca_bq = (const float*)d_in[11];
    const float* ca_wk = (const float*)d_in[12];
    const float* ca_bk = (const float*)d_in[13];
    const float* ca_wv = (const float*)d_in[14];
    const float* ca_bv = (const float*)d_in[15];
    const float* ln2_g = (const float*)d_in[16];
    const float* ln2_b = (const float*)d_in[17];
    const float* fc1_w = (const float*)d_in[18];
    const float* fc1_b = (const float*)d_in[19];
    const float* fc2_w = (const float*)d_in[20];
    const float* fc2_b = (const float*)d_in[21];
    const float* ln3_g = (const float*)d_in[22];
    const float* ln3_b = (const float*)d_in[23];

    float *q, *k, *v, *ctx, *x1, *x2, *ffn;
    cudaGetSymbolAddress((void**)&q,   g_q);
    cudaGetSymbolAddress((void**)&k,   g_k);
    cudaGetSymbolAddress((void**)&v,   g_v);
    cudaGetSymbolAddress((void**)&ctx, g_ctx);
    cudaGetSymbolAddress((void**)&x1,  g_x1);
    cudaGetSymbolAddress((void**)&x2,  g_x2);
    cudaGetSymbolAddress((void**)&ffn, g_ffn);

    cudaFuncSetAttribute(attention_tc_kernel,
                         cudaFuncAttributeMaxDynamicSharedMemorySize, ATT3_SMEM);
    cudaFuncSetAttribute(gemm_cp_kernel<0>,
                         cudaFuncAttributeMaxDynamicSharedMemorySize, GEMM_SMEM);
    cudaFuncSetAttribute(gemm_cp_kernel<1>,
                         cudaFuncAttributeMaxDynamicSharedMemorySize, GEMM_SMEM);

    const dim3 att_grid(SEQLEN / AQ2, N_HEADS, BATCH);

    // ---- self-attention: fused QKV projection (one launch) ----
    gemm_cp_kernel<0><<<dim3(24, 32), 256, GEMM_SMEM>>>(
        hid, sa_wq, sa_bq, q,
        hid, sa_wk, sa_bk, k,
        hid, sa_wv, sa_bv, v,
        NTOK, D_MODEL, D_MODEL, 8);
    attention_tc_kernel<<<att_grid, 256, ATT3_SMEM>>>(q, k, v, ctx);
    add_ln_kernel<<<NTOK, 256>>>(hid, ctx, ln1_g, ln1_b, x1);

    // ---- cross-attention: fused Q(from x1), K,V(from enc) in one launch ----
    gemm_cp_kernel<0><<<dim3(24, 32), 256, GEMM_SMEM>>>(
        x1,  ca_wq, ca_bq, q,
        enc, ca_wk, ca_bk, k,
        enc, ca_wv, ca_bv, v,
        NTOK, D_MODEL, D_MODEL, 8);
    attention_tc_kernel<<<att_grid, 256, ATT3_SMEM>>>(q, k, v, ctx);
    add_ln_kernel<<<NTOK, 256>>>(x1, ctx, ln2_g, ln2_b, x2);

    // ---- feed-forward ----
    gemm_cp_kernel<1><<<dim3(32, 32), 256, GEMM_SMEM>>>(
        x2, fc1_w, fc1_b, ffn,
        x2, fc1_w, fc1_b, ffn,
        x2, fc1_w, fc1_b, ffn,
        NTOK, FFN_DIM, D_MODEL, 32);
    gemm_cp_kernel<0><<<dim3(8, 32), 256, GEMM_SMEM>>>(
        ffn, fc2_w, fc2_b, ctx,
        ffn, fc2_w, fc2_b, ctx,
        ffn, fc2_w, fc2_b, ctx,
        NTOK, D_MODEL, FFN_DIM, 8);
    add_ln_kernel<<<NTOK, 256>>>(x2, ctx, ln3_g, ln3_b, (float*)d_out);
}